// round 6
// baseline (speedup 1.0000x reference)
#include <cuda_runtime.h>
#include <cuda_bf16.h>
#include <math.h>
#include <stdint.h>

typedef unsigned long long u64;

// ---------------------------------------------------------------------------
// Output layout (tuple flattened in order):
// offsets [4,256,256,2], sizes [4,256,256,2], weights [4,256,256,1],
// pred_cls [4,3], seg_sel [256,32,32,1], score_sel [256,1]
// ---------------------------------------------------------------------------
#define OFF_OFFSETS 0
#define OFF_SIZES   524288
#define OFF_WEIGHTS 1048576
#define OFF_PREDCLS 1310720
#define OFF_SEG     1310732
#define OFF_SCORE   1572876

// Scratch (device globals; no allocation allowed)
__device__ __nv_bfloat16 g_f1h[33554432], g_f1l[33554432];   // feat1 split
__device__ __nv_bfloat16 g_x1h[67108864], g_x1l[67108864];   // conv1 out split
__device__ float         g_x2[67108864];                     // conv2 out fp32
__device__ __nv_bfloat16 g_cph[16777216], g_cpl[16777216];   // crops split
__device__ __nv_bfloat16 g_s1h[25165824], g_s1l[25165824];   // sc1 out split
__device__ float         g_s2[25165824];                     // sc2 out fp32
// transposed+split weights: [cout][k9]
__device__ __nv_bfloat16 g_wcb1h[294912], g_wcb1l[294912];
__device__ __nv_bfloat16 g_wcb2h[589824], g_wcb2l[589824];
__device__ __nv_bfloat16 g_wsc1h[55296],  g_wsc1l[55296];
__device__ __nv_bfloat16 g_wsc2h[82944],  g_wsc2l[82944];
__device__ int g_cls[4];

// ---------------------------------------------------------------------------
// PTX helpers (arch-generic sm_80+: ldmatrix, mma.bf16, cp.async)
// ---------------------------------------------------------------------------
__device__ __forceinline__ uint32_t smem_u32(const void* p) {
    uint32_t a;
    asm("{ .reg .u64 t; cvta.to.shared.u64 t, %1; cvt.u32.u64 %0, t; }"
        : "=r"(a) : "l"(p));
    return a;
}
__device__ __forceinline__ void ldsm_x4(uint32_t* r, uint32_t a) {
    asm volatile("ldmatrix.sync.aligned.m8n8.x4.shared.b16 {%0,%1,%2,%3}, [%4];"
                 : "=r"(r[0]), "=r"(r[1]), "=r"(r[2]), "=r"(r[3]) : "r"(a));
}
__device__ __forceinline__ void mma_bf16(float* d, const uint32_t* a, const uint32_t* b) {
    asm volatile("mma.sync.aligned.m16n8k16.row.col.f32.bf16.bf16.f32 "
                 "{%0,%1,%2,%3}, {%4,%5,%6,%7}, {%8,%9}, {%0,%1,%2,%3};"
                 : "+f"(d[0]), "+f"(d[1]), "+f"(d[2]), "+f"(d[3])
                 : "r"(a[0]), "r"(a[1]), "r"(a[2]), "r"(a[3]),
                   "r"(b[0]), "r"(b[1]));
}
__device__ __forceinline__ void cpa16(uint32_t dst, const void* src, bool ok) {
    int sz = ok ? 16 : 0;
    asm volatile("cp.async.cg.shared.global [%0], [%1], 16, %2;"
                 :: "r"(dst), "l"(src), "r"(sz) : "memory");
}
__device__ __forceinline__ void cp_commit() {
    asm volatile("cp.async.commit_group;" ::: "memory");
}
template <int N>
__device__ __forceinline__ void cp_wait() {
    asm volatile("cp.async.wait_group %0;" :: "n"(N) : "memory");
}

// split fp32 -> bf16 hi + bf16 lo
__device__ __forceinline__ void bsplit(float v, __nv_bfloat16& h, __nv_bfloat16& l) {
    h = __float2bfloat16_rn(v);
    l = __float2bfloat16_rn(v - __bfloat162float(h));
}

// ---------------------------------------------------------------------------
// Pre-split kernels
// ---------------------------------------------------------------------------
__global__ void fsplit_kernel(const float* __restrict__ src,
                              __nv_bfloat16* __restrict__ h,
                              __nv_bfloat16* __restrict__ l, int n) {
    int i = blockIdx.x * blockDim.x + threadIdx.x;
    if (i * 4 >= n) return;
    float4 v = *(const float4*)(src + i * 4);
    __nv_bfloat16 h0, h1, h2, h3, l0, l1, l2, l3;
    bsplit(v.x, h0, l0); bsplit(v.y, h1, l1);
    bsplit(v.z, h2, l2); bsplit(v.w, h3, l3);
    __nv_bfloat162 hh0; hh0.x = h0; hh0.y = h1;
    __nv_bfloat162 hh1; hh1.x = h2; hh1.y = h3;
    __nv_bfloat162 ll0; ll0.x = l0; ll0.y = l1;
    __nv_bfloat162 ll1; ll1.x = l2; ll1.y = l3;
    *(uint2*)(h + i * 4) = make_uint2(*(uint32_t*)&hh0, *(uint32_t*)&hh1);
    *(uint2*)(l + i * 4) = make_uint2(*(uint32_t*)&ll0, *(uint32_t*)&ll1);
}

// weights [K9][COUT] fp32 -> wT [COUT][K9] bf16 hi/lo
__global__ void wprep_kernel(const float* __restrict__ w,
                             __nv_bfloat16* __restrict__ h,
                             __nv_bfloat16* __restrict__ l, int K9, int COUT) {
    int i = blockIdx.x * blockDim.x + threadIdx.x;
    if (i >= K9 * COUT) return;
    int k = i / COUT, c = i % COUT;
    __nv_bfloat16 hb, lb;
    bsplit(w[i], hb, lb);
    h[(size_t)c * K9 + k] = hb;
    l[(size_t)c * K9 + k] = lb;
}

// ---------------------------------------------------------------------------
// Tensor-core 3x3 SAME conv, pre-split bf16 operands, cp.async pipeline.
// CTA: 128 threads (4 warps = 2M x 2N). Tile M=128px (8y x 16x), N=COUT_TILE.
// Warp tile 64 x COUT_TILE/2. K chunks of 32. Double-buffered smem, 80B pitch.
// grid: (W/16, H/8, nimg * NT)
// ---------------------------------------------------------------------------
#define CONV_ASZ 10240                       // 128 rows * 80B per A component

template <int CIN, int COUT_TILE, bool RELU, bool OUT_SPLIT, int MAXB>
__global__ __launch_bounds__(128, MAXB)
void conv3x3_cp(const __nv_bfloat16* __restrict__ inh,
                const __nv_bfloat16* __restrict__ inl,
                const __nv_bfloat16* __restrict__ wth,
                const __nv_bfloat16* __restrict__ wtl,
                const float* __restrict__ bias,
                float* __restrict__ outf,
                __nv_bfloat16* __restrict__ outh,
                __nv_bfloat16* __restrict__ outl,
                int H, int W, int COUT, int NT) {
    constexpr int K9 = 9 * CIN;
    constexpr int BSZ = COUT_TILE * 80;
    constexpr int BUFSZ = 2 * CONV_ASZ + 2 * BSZ;
    extern __shared__ char sm[];
    const uint32_t sb = smem_u32(sm);
    __shared__ float sbias[COUT_TILE];

    int t = threadIdx.x, warp = t >> 5, lane = t & 31;
    int img = blockIdx.z / NT, ntile = blockIdx.z % NT;
    int cobase = ntile * COUT_TILE;
    int x0 = blockIdx.x * 16, y0 = blockIdx.y * 8;

    if (t < COUT_TILE) sbias[t] = bias[cobase + t];

    int lpy = t >> 4, lpx = t & 15;          // A: 1 thread per pixel
    bool bok = t < COUT_TILE;

    constexpr int NF = COUT_TILE / 16;       // n8 frags per N-warp (8 or 6)
    int wm = warp & 1, nw = warp >> 1;
    int nbase = nw * (COUT_TILE / 2);

    float acc[4][NF][4];
    #pragma unroll
    for (int i = 0; i < 4; i++)
        #pragma unroll
        for (int j = 0; j < NF; j++)
            #pragma unroll
            for (int q = 0; q < 4; q++) acc[i][j][q] = 0.f;

    const __nv_bfloat16* imgh = inh + (size_t)img * H * W * CIN;
    const __nv_bfloat16* imgl = inl + (size_t)img * H * W * CIN;
    const int KCH = K9 / 32;

    // issue one chunk's cp.async group
    auto issue = [&](int kc, int buf) {
        int kbase = kc * 32;
        int tap = kbase / CIN;
        int dy = tap / 3 - 1, dx = tap % 3 - 1;
        int gy = y0 + lpy + dy, gx = x0 + lpx + dx;
        bool aok = (gy >= 0 && gy < H && gx >= 0 && gx < W);
        int cy = min(max(gy, 0), H - 1), cx = min(max(gx, 0), W - 1);
        size_t ab = ((size_t)cy * W + cx) * CIN + (kbase % CIN);
        uint32_t AhiO = sb + buf * BUFSZ;
        uint32_t AloO = AhiO + CONV_ASZ;
        uint32_t BhiO = AhiO + 2 * CONV_ASZ;
        uint32_t BloO = BhiO + BSZ;
        uint32_t arow = t * 80;
        #pragma unroll
        for (int j = 0; j < 4; j++) {
            cpa16(AhiO + arow + j * 16, imgh + ab + j * 8, aok);
            cpa16(AloO + arow + j * 16, imgl + ab + j * 8, aok);
        }
        if (bok) {
            size_t bb = (size_t)(cobase + t) * K9 + kbase;
            #pragma unroll
            for (int j = 0; j < 4; j++) {
                cpa16(BhiO + arow + j * 16, wth + bb + j * 8, true);
                cpa16(BloO + arow + j * 16, wtl + bb + j * 8, true);
            }
        }
        cp_commit();
    };

    issue(0, 0);

    for (int kc = 0; kc < KCH; kc++) {
        int buf = kc & 1;
        if (kc + 1 < KCH) { issue(kc + 1, buf ^ 1); cp_wait<1>(); }
        else              { cp_wait<0>(); }
        __syncthreads();

        uint32_t AhiO = sb + buf * BUFSZ;
        uint32_t AloO = AhiO + CONV_ASZ;
        uint32_t BhiO = AhiO + 2 * CONV_ASZ;
        uint32_t BloO = BhiO + BSZ;

        #pragma unroll
        for (int k16 = 0; k16 < 2; k16++) {
            uint32_t ah[4][4], al[4][4];
            #pragma unroll
            for (int mi = 0; mi < 4; mi++) {
                uint32_t rowb = (uint32_t)((wm * 64 + mi * 16 + (lane & 15)) * 80
                                           + (k16 * 16 + (lane >> 4) * 8) * 2);
                ldsm_x4(ah[mi], AhiO + rowb);
                ldsm_x4(al[mi], AloO + rowb);
            }
            uint32_t bh[NF][2], bl[NF][2];
            #pragma unroll
            for (int p = 0; p < NF / 2; p++) {
                uint32_t addr = (uint32_t)((nbase + p * 16 + ((lane >> 4) << 3) + (lane & 7)) * 80
                                           + (k16 * 16 + ((lane >> 3) & 1) * 8) * 2);
                uint32_t r4[4];
                ldsm_x4(r4, BhiO + addr);
                bh[2 * p][0] = r4[0]; bh[2 * p][1] = r4[1];
                bh[2 * p + 1][0] = r4[2]; bh[2 * p + 1][1] = r4[3];
                ldsm_x4(r4, BloO + addr);
                bl[2 * p][0] = r4[0]; bl[2 * p][1] = r4[1];
                bl[2 * p + 1][0] = r4[2]; bl[2 * p + 1][1] = r4[3];
            }
            #pragma unroll
            for (int mi = 0; mi < 4; mi++)
                #pragma unroll
                for (int ni = 0; ni < NF; ni++) {
                    mma_bf16(acc[mi][ni], ah[mi], bh[ni]);
                    mma_bf16(acc[mi][ni], ah[mi], bl[ni]);
                    mma_bf16(acc[mi][ni], al[mi], bh[ni]);
                }
        }
        __syncthreads();
    }

    // ---- epilogue ----
    #pragma unroll
    for (int mi = 0; mi < 4; mi++) {
        int p0 = wm * 64 + mi * 16 + (lane >> 2);
        #pragma unroll
        for (int half = 0; half < 2; half++) {
            int p = p0 + half * 8;
            int gy = y0 + (p >> 4), gx = x0 + (p & 15);
            size_t pixoff = ((size_t)img * H * W + (size_t)gy * W + gx) * COUT + cobase;
            #pragma unroll
            for (int ni = 0; ni < NF; ni++) {
                int cl = nbase + ni * 8 + (lane & 3) * 2;
                float r0 = acc[mi][ni][half * 2 + 0] + sbias[cl];
                float r1 = acc[mi][ni][half * 2 + 1] + sbias[cl + 1];
                if (RELU) { r0 = fmaxf(r0, 0.f); r1 = fmaxf(r1, 0.f); }
                if (OUT_SPLIT) {
                    __nv_bfloat16 h0, h1, l0, l1;
                    bsplit(r0, h0, l0); bsplit(r1, h1, l1);
                    __nv_bfloat162 hh; hh.x = h0; hh.y = h1;
                    __nv_bfloat162 ll; ll.x = l0; ll.y = l1;
                    *(uint32_t*)(outh + pixoff + cl) = *(uint32_t*)&hh;
                    *(uint32_t*)(outl + pixoff + cl) = *(uint32_t*)&ll;
                } else {
                    *(float2*)(outf + pixoff + cl) = make_float2(r0, r1);
                }
            }
        }
    }
}

// ---------------------------------------------------------------------------
// Classification head: mean -> fc1 -> fc2 -> fc3 -> softmax/argmax
// ---------------------------------------------------------------------------
__global__ void cls_kernel(const float* __restrict__ feat5,
                           const float* __restrict__ fc1_w, const float* __restrict__ fc1_b,
                           const float* __restrict__ fc2_w, const float* __restrict__ fc2_b,
                           const float* __restrict__ fc3_w, const float* __restrict__ fc3_b,
                           float* __restrict__ out_predcls, int* __restrict__ cls) {
    int b = blockIdx.x;
    int t = threadIdx.x;  // 256
    __shared__ float g0[256], g1[256], lg[3];
    const float* f = feat5 + (size_t)b * 16 * 16 * 256;
    float s = 0.f;
    #pragma unroll 4
    for (int p = 0; p < 256; p++) s += f[p * 256 + t];
    g0[t] = s * (1.0f / 256.0f);
    __syncthreads();
    float a = fc1_b[t];
    #pragma unroll 4
    for (int k = 0; k < 256; k++) a = fmaf(g0[k], fc1_w[k * 256 + t], a);
    g1[t] = fmaxf(a, 0.f);
    __syncthreads();
    a = fc2_b[t];
    #pragma unroll 4
    for (int k = 0; k < 256; k++) a = fmaf(g1[k], fc2_w[k * 256 + t], a);
    g0[t] = fmaxf(a, 0.f);
    __syncthreads();
    if (t < 3) {
        a = fc3_b[t];
        for (int k = 0; k < 256; k++) a = fmaf(g0[k], fc3_w[k * 3 + t], a);
        lg[t] = a;
    }
    __syncthreads();
    if (t == 0) {
        float m = fmaxf(lg[0], fmaxf(lg[1], lg[2]));
        float e0 = expf(lg[0] - m), e1 = expf(lg[1] - m), e2 = expf(lg[2] - m);
        float inv = 1.f / (e0 + e1 + e2);
        out_predcls[b * 3 + 0] = e0 * inv;
        out_predcls[b * 3 + 1] = e1 * inv;
        out_predcls[b * 3 + 2] = e2 * inv;
        int c = 0;
        if (lg[1] > lg[0]) c = 1;
        if (lg[2] > lg[c]) c = 2;
        cls[b] = c;
    }
}

// ---------------------------------------------------------------------------
// Fused reg/wt conv with per-batch class selection: 5 output channels only.
// ---------------------------------------------------------------------------
__global__ void regsel_kernel(const float* __restrict__ x,
                              const float* __restrict__ reg_w, const float* __restrict__ reg_b,
                              const float* __restrict__ wt_w,  const float* __restrict__ wt_b,
                              const int* __restrict__ cls, float* __restrict__ out) {
    int b = blockIdx.z;
    int c = cls[b];
    __shared__ __align__(16) float ws[9 * 256 * 5];   // 46080 B
    int t = threadIdx.x;
    for (int i = t; i < 9 * 256; i += 256) {
        const float* rp = reg_w + (size_t)i * 12 + 4 * c;
        float* wp = ws + i * 5;
        wp[0] = rp[0]; wp[1] = rp[1]; wp[2] = rp[2]; wp[3] = rp[3];
        wp[4] = wt_w[(size_t)i * 3 + c];
    }
    __syncthreads();
    int px = blockIdx.x * 16 + (t & 15);
    int py = blockIdx.y * 16 + (t >> 4);
    float a0 = reg_b[4 * c], a1 = reg_b[4 * c + 1], a2 = reg_b[4 * c + 2],
          a3 = reg_b[4 * c + 3], a4 = wt_b[c];
    const float* xi = x + (size_t)b * 256 * 256 * 256;
    for (int tap = 0; tap < 9; tap++) {
        int yy = py + tap / 3 - 1, xx = px + tap % 3 - 1;
        if (yy < 0 || yy >= 256 || xx < 0 || xx >= 256) continue;
        const float* ip = xi + ((size_t)yy * 256 + xx) * 256;
        const float* wp = ws + tap * 256 * 5;
        #pragma unroll 2
        for (int ci = 0; ci < 256; ci += 4) {
            float4 v = *(const float4*)(ip + ci);
            float wl[20];
            const float4* w4 = (const float4*)(wp + ci * 5);
            #pragma unroll
            for (int q = 0; q < 5; q++) ((float4*)wl)[q] = w4[q];
            a0 = fmaf(v.x, wl[0], a0);  a1 = fmaf(v.x, wl[1], a1);
            a2 = fmaf(v.x, wl[2], a2);  a3 = fmaf(v.x, wl[3], a3);  a4 = fmaf(v.x, wl[4], a4);
            a0 = fmaf(v.y, wl[5], a0);  a1 = fmaf(v.y, wl[6], a1);
            a2 = fmaf(v.y, wl[7], a2);  a3 = fmaf(v.y, wl[8], a3);  a4 = fmaf(v.y, wl[9], a4);
            a0 = fmaf(v.z, wl[10], a0); a1 = fmaf(v.z, wl[11], a1);
            a2 = fmaf(v.z, wl[12], a2); a3 = fmaf(v.z, wl[13], a3); a4 = fmaf(v.z, wl[14], a4);
            a0 = fmaf(v.w, wl[15], a0); a1 = fmaf(v.w, wl[16], a1);
            a2 = fmaf(v.w, wl[17], a2); a3 = fmaf(v.w, wl[18], a3); a4 = fmaf(v.w, wl[19], a4);
        }
    }
    size_t pix = ((size_t)b * 256 + py) * 256 + px;
    out[OFF_OFFSETS + pix * 2 + 0] = a0;
    out[OFF_OFFSETS + pix * 2 + 1] = a1;
    out[OFF_SIZES   + pix * 2 + 0] = a2;
    out[OFF_SIZES   + pix * 2 + 1] = a3;
    out[OFF_WEIGHTS + pix] = a4;
}

// ---------------------------------------------------------------------------
// Bilinear crop, 32x32, one block per box; writes bf16 hi/lo.
// ---------------------------------------------------------------------------
__global__ void crop_kernel(const float* __restrict__ feat0,
                            const float* __restrict__ boxes,
                            __nv_bfloat16* __restrict__ ch,
                            __nv_bfloat16* __restrict__ cl) {
    int n = blockIdx.x;
    int b = n >> 6;
    const int H = 512, W = 512, C = 64;
    __shared__ int sy0[32], sx0[32];
    __shared__ float swy[32], swx[32];
    const float* bx = boxes + (size_t)n * 4;
    float y1 = bx[0], x1 = bx[1], y2 = bx[2], x2 = bx[3];
    int t = threadIdx.x;
    if (t < 32) {
        float tt = (float)t / 31.0f;
        float ys = y1 * (H - 1) + tt * (y2 - y1) * (H - 1);
        int yy0 = (int)floorf(ys);
        yy0 = min(max(yy0, 0), H - 2);
        sy0[t] = yy0; swy[t] = ys - (float)yy0;
    } else if (t < 64) {
        int i = t - 32;
        float tt = (float)i / 31.0f;
        float xs = x1 * (W - 1) + tt * (x2 - x1) * (W - 1);
        int xx0 = (int)floorf(xs);
        xx0 = min(max(xx0, 0), W - 2);
        sx0[i] = xx0; swx[i] = xs - (float)xx0;
    }
    __syncthreads();
    const float* f = feat0 + (size_t)b * H * W * C;
    size_t obase = (size_t)n * 32 * 32 * C;
    for (int idx = t; idx < 32 * 32 * C; idx += blockDim.x) {
        int c  = idx & 63;
        int ix = (idx >> 6) & 31;
        int iy = idx >> 11;
        int yy0 = sy0[iy], xx0 = sx0[ix];
        float wy = swy[iy], wx = swx[ix];
        const float* p00 = f + ((size_t)yy0 * W + xx0) * C + c;
        float v00 = p00[0], v01 = p00[C], v10 = p00[(size_t)W * C], v11 = p00[(size_t)W * C + C];
        float top = v00 * (1.f - wx) + v01 * wx;
        float bot = v10 * (1.f - wx) + v11 * wx;
        float v = top * (1.f - wy) + bot * wy;
        __nv_bfloat16 hb, lb;
        bsplit(v, hb, lb);
        ch[obase + idx] = hb;
        cl[obase + idx] = lb;
    }
}

// ---------------------------------------------------------------------------
// so conv with class selection: 1 output channel per crop.
// ---------------------------------------------------------------------------
__global__ void sosel_kernel(const float* __restrict__ s2,
                             const float* __restrict__ so_w, const float* __restrict__ so_b,
                             const int* __restrict__ cls, float* __restrict__ out) {
    int n = blockIdx.x;
    int c = cls[n >> 6];
    __shared__ __align__(16) float ws[9 * 96];
    int t = threadIdx.x;
    for (int i = t; i < 864; i += 256) ws[i] = so_w[(size_t)i * 3 + c];
    __syncthreads();
    float bias = so_b[c];
    const float* sp = s2 + (size_t)n * 32 * 32 * 96;
    for (int pix = t; pix < 1024; pix += 256) {
        int py = pix >> 5, px = pix & 31;
        float acc = bias;
        for (int tap = 0; tap < 9; tap++) {
            int yy = py + tap / 3 - 1, xx = px + tap % 3 - 1;
            if (yy < 0 || yy >= 32 || xx < 0 || xx >= 32) continue;
            const float* ip = sp + ((size_t)yy * 32 + xx) * 96;
            const float* wp = ws + tap * 96;
            #pragma unroll 4
            for (int ci = 0; ci < 96; ci += 4) {
                float4 v = *(const float4*)(ip + ci);
                float4 w = *(const float4*)(wp + ci);
                acc = fmaf(v.x, w.x, acc);
                acc = fmaf(v.y, w.y, acc);
                acc = fmaf(v.z, w.z, acc);
                acc = fmaf(v.w, w.w, acc);
            }
        }
        out[OFF_SEG + (size_t)n * 1024 + pix] = acc;
    }
}

// ---------------------------------------------------------------------------
// Score head: 4x4 avg pool -> dense 6144->256 -> 256->256 -> 256->3 (select)
// ---------------------------------------------------------------------------
__global__ void score_kernel(const float* __restrict__ s2,
                             const float* __restrict__ sd1_w, const float* __restrict__ sd1_b,
                             const float* __restrict__ sd2_w, const float* __restrict__ sd2_b,
                             const float* __restrict__ sd3_w, const float* __restrict__ sd3_b,
                             const int* __restrict__ cls, float* __restrict__ out) {
    int n = blockIdx.x;
    int t = threadIdx.x;  // 256
    __shared__ float pooled[6144];
    __shared__ float h1[256], h2[256];
    const float* sp = s2 + (size_t)n * 32 * 32 * 96;
    for (int o = t; o < 6144; o += 256) {
        int c  = o % 96;
        int px = (o / 96) & 7;
        int py = o / 768;
        float s = 0.f;
        #pragma unroll
        for (int i = 0; i < 4; i++)
            #pragma unroll
            for (int j = 0; j < 4; j++)
                s += sp[(((size_t)(py * 4 + i)) * 32 + (px * 4 + j)) * 96 + c];
        pooled[o] = s * (1.f / 16.f);
    }
    __syncthreads();
    float a = sd1_b[t];
    #pragma unroll 4
    for (int k = 0; k < 6144; k++) a = fmaf(pooled[k], sd1_w[(size_t)k * 256 + t], a);
    h1[t] = fmaxf(a, 0.f);
    __syncthreads();
    a = sd2_b[t];
    #pragma unroll 4
    for (int k = 0; k < 256; k++) a = fmaf(h1[k], sd2_w[k * 256 + t], a);
    h2[t] = fmaxf(a, 0.f);
    __syncthreads();
    if (t == 0) {
        int c = cls[n >> 6];
        float acc = sd3_b[c];
        for (int k = 0; k < 256; k++) acc = fmaf(h2[k], sd3_w[k * 3 + c], acc);
        out[OFF_SCORE + n] = acc;
    }
}

// ---------------------------------------------------------------------------
extern "C" void kernel_launch(void* const* d_in, const int* in_sizes, int n_in,
                              void* d_out, int out_size) {
    (void)in_sizes; (void)n_in; (void)out_size;
    const float* feat0 = (const float*)d_in[0];
    const float* feat1 = (const float*)d_in[1];
    const float* feat5 = (const float*)d_in[2];
    const float* boxes = (const float*)d_in[3];
    const float* cb1_w = (const float*)d_in[4];
    const float* cb1_b = (const float*)d_in[5];
    const float* cb2_w = (const float*)d_in[6];
    const float* cb2_b = (const float*)d_in[7];
    const float* reg_w = (const float*)d_in[8];
    const float* reg_b = (const float*)d_in[9];
    const float* wt_w  = (const float*)d_in[10];
    const float* wt_b  = (const float*)d_in[11];
    const float* fc1_w = (const float*)d_in[12];
    const float* fc1_b = (const float*)d_in[13];
    const float* fc2_w = (const float*)d_in[14];
    const float* fc2_b = (const float*)d_in[15];
    const float* fc3_w = (const float*)d_in[16];
    const float* fc3_b = (const float*)d_in[17];
    const float* sc1_w = (const float*)d_in[18];
    const float* sc1_b = (const float*)d_in[19];
    const float* sc2_w = (const float*)d_in[20];
    const float* sc2_b = (const float*)d_in[21];
    const float* so_w  = (const float*)d_in[22];
    const float* so_b  = (const float*)d_in[23];
    const float* sd1_w = (const float*)d_in[24];
    const float* sd1_b = (const float*)d_in[25];
    const float* sd2_w = (const float*)d_in[26];
    const float* sd2_b = (const float*)d_in[27];
    const float* sd3_w = (const float*)d_in[28];
    const float* sd3_b = (const float*)d_in[29];
    float* out = (float*)d_out;

    // resolve device globals
    void *pf1h, *pf1l, *px1h, *px1l, *px2, *pcph, *pcpl, *ps1h, *ps1l, *ps2, *pcls;
    void *pw1h, *pw1l, *pw2h, *pw2l, *pw3h, *pw3l, *pw4h, *pw4l;
    cudaGetSymbolAddress(&pf1h, g_f1h);  cudaGetSymbolAddress(&pf1l, g_f1l);
    cudaGetSymbolAddress(&px1h, g_x1h);  cudaGetSymbolAddress(&px1l, g_x1l);
    cudaGetSymbolAddress(&px2, g_x2);
    cudaGetSymbolAddress(&pcph, g_cph);  cudaGetSymbolAddress(&pcpl, g_cpl);
    cudaGetSymbolAddress(&ps1h, g_s1h);  cudaGetSymbolAddress(&ps1l, g_s1l);
    cudaGetSymbolAddress(&ps2, g_s2);
    cudaGetSymbolAddress(&pcls, g_cls);
    cudaGetSymbolAddress(&pw1h, g_wcb1h); cudaGetSymbolAddress(&pw1l, g_wcb1l);
    cudaGetSymbolAddress(&pw2h, g_wcb2h); cudaGetSymbolAddress(&pw2l, g_wcb2l);
    cudaGetSymbolAddress(&pw3h, g_wsc1h); cudaGetSymbolAddress(&pw3l, g_wsc1l);
    cudaGetSymbolAddress(&pw4h, g_wsc2h); cudaGetSymbolAddress(&pw4l, g_wsc2l);
    __nv_bfloat16 *f1h = (__nv_bfloat16*)pf1h, *f1l = (__nv_bfloat16*)pf1l;
    __nv_bfloat16 *x1h = (__nv_bfloat16*)px1h, *x1l = (__nv_bfloat16*)px1l;
    __nv_bfloat16 *cph = (__nv_bfloat16*)pcph, *cpl = (__nv_bfloat16*)pcpl;
    __nv_bfloat16 *s1h = (__nv_bfloat16*)ps1h, *s1l = (__nv_bfloat16*)ps1l;
    __nv_bfloat16 *w1h = (__nv_bfloat16*)pw1h, *w1l = (__nv_bfloat16*)pw1l;
    __nv_bfloat16 *w2h = (__nv_bfloat16*)pw2h, *w2l = (__nv_bfloat16*)pw2l;
    __nv_bfloat16 *w3h = (__nv_bfloat16*)pw3h, *w3l = (__nv_bfloat16*)pw3l;
    __nv_bfloat16 *w4h = (__nv_bfloat16*)pw4h, *w4l = (__nv_bfloat16*)pw4l;
    float *x2 = (float*)px2, *s2 = (float*)ps2;
    int* cls = (int*)pcls;

    // dynamic smem opt-in (idempotent host calls; capture-safe)
    constexpr int DYN128 = 2 * (2 * CONV_ASZ + 2 * 128 * 80);   // 81920
    constexpr int DYN96  = 2 * (2 * CONV_ASZ + 2 * 96 * 80);    // 71680
    cudaFuncSetAttribute(conv3x3_cp<128, 128, true, true,  2>,
                         cudaFuncAttributeMaxDynamicSharedMemorySize, DYN128);
    cudaFuncSetAttribute(conv3x3_cp<256, 128, true, false, 2>,
                         cudaFuncAttributeMaxDynamicSharedMemorySize, DYN128);
    cudaFuncSetAttribute(conv3x3_cp<64, 96, true, true,  3>,
                         cudaFuncAttributeMaxDynamicSharedMemorySize, DYN96);
    cudaFuncSetAttribute(conv3x3_cp<96, 96, true, false, 3>,
                         cudaFuncAttributeMaxDynamicSharedMemorySize, DYN96);

    // classification first (reg/seg selection depends on cls)
    cls_kernel<<<4, 256>>>(feat5, fc1_w, fc1_b, fc2_w, fc2_b, fc3_w, fc3_b,
                           out + OFF_PREDCLS, cls);

    // operand preparation (split/transposed weights + feat1)
    wprep_kernel<<<(1152 * 256 + 255) / 256, 256>>>(cb1_w, w1h, w1l, 1152, 256);
    wprep_kernel<<<(2304 * 256 + 255) / 256, 256>>>(cb2_w, w2h, w2l, 2304, 256);
    wprep_kernel<<<(576 * 96 + 255) / 256, 256>>>(sc1_w, w3h, w3l, 576, 96);
    wprep_kernel<<<(864 * 96 + 255) / 256, 256>>>(sc2_w, w4h, w4l, 864, 96);
    fsplit_kernel<<<(33554432 / 4 + 255) / 256, 256>>>(feat1, f1h, f1l, 33554432);

    // crop + segmentation branch
    crop_kernel<<<256, 256>>>(feat0, boxes, cph, cpl);
    conv3x3_cp<64, 96, true, true, 3><<<dim3(2, 4, 256), 128, DYN96>>>(
        cph, cpl, w3h, w3l, sc1_b, nullptr, s1h, s1l, 32, 32, 96, 1);
    conv3x3_cp<96, 96, true, false, 3><<<dim3(2, 4, 256), 128, DYN96>>>(
        s1h, s1l, w4h, w4l, sc2_b, s2, nullptr, nullptr, 32, 32, 96, 1);
    sosel_kernel<<<256, 256>>>(s2, so_w, so_b, cls, out);
    score_kernel<<<256, 256>>>(s2, sd1_w, sd1_b, sd2_w, sd2_b, sd3_w, sd3_b, cls, out);

    // regression branch
    conv3x3_cp<128, 128, true, true, 2><<<dim3(16, 32, 8), 128, DYN128>>>(
        f1h, f1l, w1h, w1l, cb1_b, nullptr, x1h, x1l, 256, 256, 256, 2);
    conv3x3_cp<256, 128, true, false, 2><<<dim3(16, 32, 8), 128, DYN128>>>(
        x1h, x1l, w2h, w2l, cb2_b, x2, nullptr, nullptr, 256, 256, 256, 2);
    regsel_kernel<<<dim3(16, 16, 4), 256>>>(x2, reg_w, reg_b, wt_w, wt_b, cls, out);
}